// round 9
// baseline (speedup 1.0000x reference)
#include <cuda_runtime.h>
#include <cuda_fp16.h>
#include <math.h>
#include <stdint.h>

// ---------------- problem constants ----------------
#define BB   2
#define SS   1024
#define DD   2048
#define HH   16
#define FF   8192
#define DHD  128
#define HALF 64
#define MM   (BB*SS)          // 2048 rows
#define KAUG (2*DHD)          // 256 augmented K dim

#define HS    0.05f
#define BETA  0.3f
#define ALPHA 0.5f
#define CLIPV 10.0f
#define EPSV  1e-6f
#define SCALE 0.08838834764831845f   // 1/sqrt(128)
#define SQLAM 0.31622776601683794f   // sqrt(0.1)

// ---------------- static device scratch ----------------
static __device__ __align__(128) __half g_xn  [MM*DD];          // rmsnorm/mix out (GEMM A)
static __device__ __align__(128) __half g_tmp [MM*3*DD];        // QKV GEMM out (fp16)
static __device__ __align__(128) float  g_cur [MM*DD];
static __device__ __align__(128) float  g_h1  [MM*DD];
static __device__ __align__(128) __half g_qa  [BB*HH*SS*KAUG];
static __device__ __align__(128) __half g_ka  [BB*HH*SS*KAUG];
static __device__ __align__(128) __half g_vt  [BB*HH*DHD*SS];   // per-head [DHD, S]
static __device__ __align__(128) float  g_ao  [BB*HH*SS*DHD];   // unnormalized PV out
static __device__ __align__(128) float  g_inv [BB*HH*SS];       // per-row 1/sum
static __device__ __align__(128) __half g_sc  [(long long)BB*HH*SS*SS];  // scores fp16
static __device__ __align__(128) __half g_ph  [(long long)BB*HH*SS*SS];  // unnorm probs fp16
static __device__ __align__(128) __half g_gu  [MM*2*FF];        // FFN gate|up out (fp16)
static __device__ __align__(128) __half g_hh  [MM*FF];          // FFN hidden (GEMM A)
// fp16 weights (stacked)
static __device__ __align__(128) __half g_wqkv[3*DD*DD];
static __device__ __align__(128) __half g_wo  [DD*DD];
static __device__ __align__(128) __half g_wgu [2*FF*DD];
static __device__ __align__(128) __half g_wd  [DD*FF];

// ---------------- helpers ----------------
__device__ __forceinline__ uint32_t smem_u32(const void* p) {
    uint32_t a;
    asm("{ .reg .u64 t; cvta.to.shared.u64 t, %1; cvt.u32.u64 %0, t; }" : "=r"(a) : "l"(p));
    return a;
}
__device__ __forceinline__ void cpasync16(uint32_t dst, const void* src) {
    asm volatile("cp.async.cg.shared.global [%0], [%1], 16;" :: "r"(dst), "l"(src));
}
#define CP_COMMIT()  asm volatile("cp.async.commit_group;" ::: "memory")
#define CP_WAIT2()   asm volatile("cp.async.wait_group 2;" ::: "memory")

__device__ __forceinline__ void ldmx4(uint32_t* r, uint32_t addr) {
    asm volatile("ldmatrix.sync.aligned.m8n8.x4.shared.b16 {%0,%1,%2,%3}, [%4];"
        : "=r"(r[0]), "=r"(r[1]), "=r"(r[2]), "=r"(r[3]) : "r"(addr));
}
__device__ __forceinline__ void mma16816(float* c, const uint32_t* a, uint32_t b0, uint32_t b1) {
    asm volatile("mma.sync.aligned.m16n8k16.row.col.f32.f16.f16.f32 "
        "{%0,%1,%2,%3}, {%4,%5,%6,%7}, {%8,%9}, {%0,%1,%2,%3};"
        : "+f"(c[0]), "+f"(c[1]), "+f"(c[2]), "+f"(c[3])
        : "r"(a[0]), "r"(a[1]), "r"(a[2]), "r"(a[3]), "r"(b0), "r"(b1));
}

// ---------------- fp16 tensor-core GEMM (BM=128, 4 warps, 64x64 warp tiles) ----------------
// C[M,N](TO) = A[M,K](f16) * B[N,K](f16)^T  (+= if ADD; ADD only with TO=float)
// CTA tile 128x128, chunk = 64 halves (128B rows), 3-stage cp.async, 2 CTA/SM.
// 4 warps (2m x 2n), warp tile 64x64 (square = min smem fragment traffic),
// ldmatrix.x4, XOR-swizzled smem.
// TRI: blockIdx.x enumerates lower-triangle 128x128 blocks (causal scores).
// PVK: K limited to (blockIdx.y+1)*128 halves (causal PV).
#define HSTAGE 32768    // A:128 rows + B:128 rows, 128B each
#define HSMEM  (3*HSTAGE)

template<typename TO, bool ADD, bool TRI, bool PVK>
__global__ void __launch_bounds__(128, 2) hgemm(
    const __half* __restrict__ A, const __half* __restrict__ B, TO* __restrict__ C,
    int Kn, int Nn, long long sA, long long sB, long long sC)
{
    extern __shared__ __align__(128) char sm[];
    const uint32_t sbase = smem_u32(sm);

    int bi, bj;
    if (TRI) {
        int x = blockIdx.x, i = 0;
        while ((i + 1) * (i + 2) / 2 <= x) i++;
        bi = i; bj = x - i * (i + 1) / 2;
    } else { bi = blockIdx.y; bj = blockIdx.x; }

    A += (long long)blockIdx.z * sA + (long long)(bi * 128) * Kn;
    B += (long long)blockIdx.z * sB + (long long)(bj * 128) * Kn;
    C += (long long)blockIdx.z * sC;

    const int NC = PVK ? 2 * (blockIdx.y + 1) : (Kn >> 6);

    const int tid = threadIdx.x, warp = tid >> 5, lane = tid & 31;
    const int gid = lane >> 2, tig = lane & 3;
    const int wm = (warp & 1) * 64, wn = (warp >> 1) * 64;

    const int mi = lane >> 3, ri = lane & 7;
    const int fro = (mi & 1) * 8 + ri;
    const int khalf = mi >> 1;

    float acc[4][8][4];
#pragma unroll
    for (int mt = 0; mt < 4; mt++)
#pragma unroll
        for (int nt = 0; nt < 8; nt++)
#pragma unroll
            for (int j = 0; j < 4; j++) acc[mt][nt][j] = 0.f;

    const int lr = tid >> 3;        // 0..15
    const int lseg = tid & 7;       // 16B segment

    // empty-commit padding when chunk >= NC keeps wait_group counts uniform
    auto load = [&](int chunk, int s) {
        if (chunk < NC) {
            const uint32_t st = sbase + (uint32_t)s * HSTAGE;
            const __half* Ag = A + chunk * 64;
            const __half* Bg = B + chunk * 64;
#pragma unroll
            for (int it = 0; it < 8; it++) {
                int r = lr + it * 16;
                uint32_t off = (uint32_t)(r * 128 + ((lseg ^ (r & 7)) << 4));
                cpasync16(st + off,         Ag + (long long)r * Kn + lseg * 8);
                cpasync16(st + 16384 + off, Bg + (long long)r * Kn + lseg * 8);
            }
        }
        CP_COMMIT();
    };

    load(0, 0);
    load(1, 1);
    load(2, 2);

    const int arow[4] = { wm + fro, wm + 16 + fro, wm + 32 + fro, wm + 48 + fro };
    const int brow[4] = { wn + fro, wn + 16 + fro, wn + 32 + fro, wn + 48 + fro };

    int s = 0;
    for (int c = 0; c < NC; c++) {
        CP_WAIT2();                       // stage s complete (2 groups may be pending)
        __syncthreads();

        const uint32_t st = sbase + (uint32_t)s * HSTAGE;
#pragma unroll
        for (int kb = 0; kb < 64; kb += 16) {
            const int ks = (kb >> 3) + khalf;
            uint32_t a[4][4], b[4][4];
#pragma unroll
            for (int mt = 0; mt < 4; mt++) {
                int r = arow[mt];
                ldmx4(a[mt], st + (uint32_t)(r * 128 + ((ks ^ (r & 7)) << 4)));
            }
#pragma unroll
            for (int np = 0; np < 4; np++) {
                int r = brow[np];
                ldmx4(b[np], st + 16384u + (uint32_t)(r * 128 + ((ks ^ (r & 7)) << 4)));
            }
#pragma unroll
            for (int mt = 0; mt < 4; mt++)
#pragma unroll
                for (int nt = 0; nt < 8; nt++)
                    mma16816(acc[mt][nt], a[mt], b[nt >> 1][nt & 1], b[nt >> 1][2 + (nt & 1)]);
        }
        __syncthreads();
        load(c + 3, s);                   // pads with empty commit past NC
        s = (s == 2) ? 0 : s + 1;
    }

    // epilogue
#pragma unroll
    for (int mt = 0; mt < 4; mt++) {
        int r0 = bi * 128 + wm + mt * 16 + gid;
#pragma unroll
        for (int nt = 0; nt < 8; nt++) {
            int cc = bj * 128 + wn + nt * 8 + 2 * tig;
            TO* p0 = C + (long long)r0 * Nn + cc;
            TO* p1 = p0 + 8 * (long long)Nn;
            if constexpr (sizeof(TO) == 2) {
                *(__half2*)p0 = __floats2half2_rn(acc[mt][nt][0], acc[mt][nt][1]);
                *(__half2*)p1 = __floats2half2_rn(acc[mt][nt][2], acc[mt][nt][3]);
            } else if (ADD) {
                p0[0] += acc[mt][nt][0]; p0[1] += acc[mt][nt][1];
                p1[0] += acc[mt][nt][2]; p1[1] += acc[mt][nt][3];
            } else {
                p0[0] = acc[mt][nt][0]; p0[1] = acc[mt][nt][1];
                p1[0] = acc[mt][nt][2]; p1[1] = acc[mt][nt][3];
            }
        }
    }
}

// ---------------- RMSNorm -> fp16 ----------------
__global__ void rmsnorm_k(const float* __restrict__ x, const float* __restrict__ sc,
                          __half* __restrict__ o)
{
    const int row = blockIdx.x;
    const float* xr = x + (long long)row * DD;
    __half*      orw = o + (long long)row * DD;
    float s = 0.f;
    for (int j = threadIdx.x; j < DD; j += 256) { float v = xr[j]; s += v * v; }
    __shared__ float red[256];
    red[threadIdx.x] = s; __syncthreads();
    for (int t = 128; t > 0; t >>= 1) {
        if (threadIdx.x < t) red[threadIdx.x] += red[threadIdx.x + t];
        __syncthreads();
    }
    float r = rsqrtf(red[0] * (1.0f / DD) + EPSV);
    for (int j = threadIdx.x; j < DD; j += 256) orw[j] = __float2half(xr[j] * r * sc[j]);
}

// ---------------- RoPE + augment (Q and K together) from tmp[M,3D] fp16 ----------------
__global__ void rope_aug2_k(const __half* __restrict__ t,
                            __half* __restrict__ qa, __half* __restrict__ ka)
{
    int idx = blockIdx.x * 256 + threadIdx.x;     // B*S*H*HALF threads
    int d = idx & 63;
    int h = (idx >> 6) & 15;
    int s = (idx >> 10) & 1023;
    int b = idx >> 20;
    const __half* row = t + ((long long)b * SS + s) * (3 * DD);
    float q1 = __half2float(row[h * DHD + d]);
    float q2 = __half2float(row[h * DHD + HALF + d]);
    float k1 = __half2float(row[DD + h * DHD + d]);
    float k2 = __half2float(row[DD + h * DHD + HALF + d]);
    float inv = __expf(-(float)d * (9.210340371976184f / 64.0f));
    float ang = (float)s * inv;
    float cs, sn; __sincosf(ang, &sn, &cs);
    long long base = (((long long)(b * HH + h)) * SS + s) * KAUG;
    float qo1 = q1 * cs - q2 * sn, qo2 = q1 * sn + q2 * cs;
    float ko1 = k1 * cs - k2 * sn, ko2 = k1 * sn + k2 * cs;
    qa[base + d]              = __float2half(qo1);
    qa[base + HALF + d]       = __float2half(qo2);
    qa[base + DHD + d]        = __float2half(SQLAM * qo1 * qo1);
    qa[base + DHD + HALF + d] = __float2half(SQLAM * qo2 * qo2);
    ka[base + d]              = __float2half(ko1);
    ka[base + HALF + d]       = __float2half(ko2);
    ka[base + DHD + d]        = __float2half(SQLAM * ko1 * ko1);
    ka[base + DHD + HALF + d] = __float2half(SQLAM * ko2 * ko2);
}

// ---------------- V transpose from tmp[M,3D] fp16 -> per-head [DHD,S] ----------------
__global__ void vt_k(const __half* __restrict__ t, __half* __restrict__ out)
{
    __shared__ __half tl[32][33];
    int bh = blockIdx.z;
    int b = bh >> 4, h = bh & 15;
    int s0 = blockIdx.x * 32, d0 = blockIdx.y * 32;
    int tx = threadIdx.x & 31, ty = threadIdx.x >> 5;
    for (int i = ty; i < 32; i += 8) {
        int s = s0 + i, d = d0 + tx;
        tl[i][tx] = t[((long long)(b * SS + s)) * (3 * DD) + 2 * DD + h * DHD + d];
    }
    __syncthreads();
    for (int i = ty; i < 32; i += 8) {
        int d = d0 + i, s = s0 + tx;
        out[((long long)bh * DHD + d) * SS + s] = tl[tx][i];
    }
}

// ---------------- causal softmax: fp16 scores in, single exp, unnormalized out ----------------
__global__ void softmax_k(const __half* __restrict__ sc, __half* __restrict__ ph,
                          float* __restrict__ inv)
{
    long long row = blockIdx.x;
    int i = (int)(row % SS);
    int lim = i | 127;                    // zero-fill out to PV block boundary
    const __half* p = sc + row * SS;
    __half* q = ph + row * SS;
    int tid = threadIdx.x;
    __shared__ float red[256];

    float v[4];
    float m = -1e30f;
#pragma unroll
    for (int k = 0; k < 4; k++) {
        int j = tid + 256 * k;
        v[k] = (j <= i) ? __half2float(p[j]) * SCALE : -1e30f;
        m = fmaxf(m, v[k]);
    }
    red[tid] = m; __syncthreads();
    for (int t = 128; t > 0; t >>= 1) {
        if (tid < t) red[tid] = fmaxf(red[tid], red[tid + t]);
        __syncthreads();
    }
    m = red[0]; __syncthreads();

    float sum = 0.f;
#pragma unroll
    for (int k = 0; k < 4; k++) {
        int j = tid + 256 * k;
        if (j <= i) {
            float e = __expf(v[k] - m);
            q[j] = __float2half(e);
            sum += e;
        } else if (j <= lim) {
            q[j] = __half(0.f);
        }
    }
    red[tid] = sum; __syncthreads();
    for (int t = 128; t > 0; t >>= 1) {
        if (tid < t) red[tid] += red[tid + t];
        __syncthreads();
    }
    if (tid == 0) inv[row] = 1.f / red[0];
}

// ---------------- normalize + hadamard mix + transpose -> fp16 [M,D] ----------------
__global__ void mix_transpose_k(const float* __restrict__ ao, const float* __restrict__ inv,
                                __half* __restrict__ out)
{
    int idx = blockIdx.x * 256 + threadIdx.x;
    int d  = idx & 127;
    int s  = (idx >> 7) & 1023;
    int bh = idx >> 17;
    int h = bh & 15, b = bh >> 4;
    float iv = inv[(long long)bh * SS + s];
    float v  = ao[idx] * iv;
    float pv = ao[(idx - d) | ((d + 127) & 127)] * iv;
    out[((long long)(b * SS + s)) * DD + h * DHD + d] = __float2half(v * (1.f + HS * pv));
}

// ---------------- fused silu*up + hadamard mix -> fp16 hidden ----------------
__global__ void silu_mix_k(const __half* __restrict__ gu, __half* __restrict__ hh)
{
    int i = blockIdx.x * 256 + threadIdx.x;       // M*F threads
    int m = i >> 13;                               // F = 8192
    int c = i & (FF - 1);
    const __half* row = gu + (long long)m * (2 * FF);
    int pc = (c + FF - 1) & (FF - 1);
    float g  = __half2float(row[c]),  u  = __half2float(row[FF + c]);
    float g2 = __half2float(row[pc]), u2 = __half2float(row[FF + pc]);
    float h  = g  / (1.f + __expf(-g))  * u;
    float h2 = g2 / (1.f + __expf(-g2)) * u2;
    hh[i] = __float2half(h * (1.f + HS * h2));
}

// ---------------- misc elementwise ----------------
__global__ void copy_k(float* __restrict__ dst, const float* __restrict__ src, int n)
{ int i = blockIdx.x * 256 + threadIdx.x; if (i < n) dst[i] = src[i]; }

// vectorized fp32->fp16 (n divisible by 4)
__global__ void w2h_k(__half* __restrict__ dst, const float* __restrict__ src, int n4)
{
    int i = blockIdx.x * 256 + threadIdx.x;
    if (i < n4) {
        float4 v = ((const float4*)src)[i];
        __half2 lo = __floats2half2_rn(v.x, v.y);
        __half2 hi = __floats2half2_rn(v.z, v.w);
        ((uint2*)dst)[i] = make_uint2(*(uint32_t*)&lo, *(uint32_t*)&hi);
    }
}

__global__ void x2_k(float* __restrict__ cur, const float* __restrict__ h1,
                     const float* __restrict__ x, int n)
{ int i = blockIdx.x * 256 + threadIdx.x; if (i < n) cur[i] = (1.f + BETA) * h1[i] - BETA * x[i]; }

__global__ void final_k(float* __restrict__ out, const float* __restrict__ h1,
                        const float* __restrict__ h2, int n)
{
    int i = blockIdx.x * 256 + threadIdx.x;
    if (i < n) {
        float v = ALPHA * h1[i] + (1.f - ALPHA) * h2[i];
        out[i] = fminf(fmaxf(v, -CLIPV), CLIPV);
    }
}

// ---------------- host orchestration ----------------
static void run_pass(const __half* wqkv, const __half* wo, const __half* wgu, const __half* wd,
                     const float* na, const float* nb,
                     float* cur, __half* xn, __half* tmp,
                     __half* qa, __half* ka, __half* vt, float* ao, float* inv,
                     __half* sc, __half* ph, __half* gu, __half* hh)
{
    const int nMD = MM * DD, nMF = MM * FF;

    rmsnorm_k<<<MM, 256>>>(cur, na, xn);

    // fused QKV: [M, 3D](fp16) = xn * wqkv^T
    hgemm<__half,false,false,false><<<dim3(3*DD/128, MM/128, 1), 128, HSMEM>>>(
        xn, wqkv, tmp, DD, 3*DD, 0, 0, 0);
    rope_aug2_k<<<(BB*SS*HH*HALF)/256, 256>>>(tmp, qa, ka);
    vt_k<<<dim3(SS/32, DHD/32, BB*HH), 256>>>(tmp, vt);

    // causal scores (fp16 out): lower-triangle blocks only
    hgemm<__half,false,true,false><<<dim3(36, 1, BB*HH), 128, HSMEM>>>(
        qa, ka, sc, KAUG, SS,
        (long long)SS*KAUG, (long long)SS*KAUG, (long long)SS*SS);
    softmax_k<<<BB*HH*SS, 256>>>(sc, ph, inv);
    // PV with causal K truncation (unnormalized probs)
    hgemm<float,false,false,true><<<dim3(1, SS/128, BB*HH), 128, HSMEM>>>(
        ph, vt, ao, SS, DHD,
        (long long)SS*SS, (long long)SS*DHD, (long long)SS*DHD);

    mix_transpose_k<<<nMD/256, 256>>>(ao, inv, xn);
    hgemm<float,true,false,false><<<dim3(DD/128, MM/128, 1), 128, HSMEM>>>(
        xn, wo, cur, DD, DD, 0, 0, 0);

    rmsnorm_k<<<MM, 256>>>(cur, nb, xn);
    // fused gate|up: [M, 2F](fp16)
    hgemm<__half,false,false,false><<<dim3(2*FF/128, MM/128, 1), 128, HSMEM>>>(
        xn, wgu, gu, DD, 2*FF, 0, 0, 0);
    silu_mix_k<<<nMF/256, 256>>>(gu, hh);
    hgemm<float,true,false,false><<<dim3(DD/128, MM/128, 1), 128, HSMEM>>>(
        hh, wd, cur, FF, DD, 0, 0, 0);
}

extern "C" void kernel_launch(void* const* d_in, const int* in_sizes, int n_in,
                              void* d_out, int out_size)
{
    (void)in_sizes; (void)n_in; (void)out_size;
    const float* x   = (const float*)d_in[0];
    const float* Wq0 = (const float*)d_in[1];
    const float* Wk0 = (const float*)d_in[2];
    const float* Wv0 = (const float*)d_in[3];
    const float* Wo0 = (const float*)d_in[4];
    // d_in[5] = gate_w: unused (rotate_half invariance => o2 == o1)
    const float* n1 = (const float*)d_in[6];
    const float* n2 = (const float*)d_in[7];
    const float* n3 = (const float*)d_in[8];
    const float* n4 = (const float*)d_in[9];
    const float* Wg0 = (const float*)d_in[10];
    const float* Wu0 = (const float*)d_in[11];
    const float* Wd0 = (const float*)d_in[12];
    float* out = (float*)d_out;

    cudaFuncSetAttribute(hgemm<__half,false,false,false>, cudaFuncAttributeMaxDynamicSharedMemorySize, HSMEM);
    cudaFuncSetAttribute(hgemm<float,true,false,false>,   cudaFuncAttributeMaxDynamicSharedMemorySize, HSMEM);
    cudaFuncSetAttribute(hgemm<__half,false,true,false>,  cudaFuncAttributeMaxDynamicSharedMemorySize, HSMEM);
    cudaFuncSetAttribute(hgemm<float,false,false,true>,   cudaFuncAttributeMaxDynamicSharedMemorySize, HSMEM);

    __half *xn, *tmp, *qa, *ka, *vt, *sc, *ph, *gu, *hh, *wqkv, *wo, *wgu, *wd;
    float *cur, *h1, *ao, *inv;
    cudaGetSymbolAddress((void**)&xn,  g_xn);
    cudaGetSymbolAddress((void**)&tmp, g_tmp);
    cudaGetSymbolAddress((void**)&cur, g_cur);
    cudaGetSymbolAddress((void**)&h1,  g_h1);
    cudaGetSymbolAddress((void**)&qa,  g_qa);
    cudaGetSymbolAddress((void**)&ka,  g_ka);
    cudaGetSymbolAddress((void**)&vt,  g_vt);
    cudaGetSymbolAddress((void**)&ao,  g_ao);
    cudaGetSymbolAddress((void**)&inv, g_inv);
    cudaGetSymbolAddress((void**)&sc,  g_sc);
    cudaGetSymbolAddress((void**)&ph,  g_ph);
    cudaGetSymbolAddress((void**)&gu,  g_gu);
    cudaGetSymbolAddress((void**)&hh,  g_hh);
    cudaGetSymbolAddress((void**)&wqkv,g_wqkv);
    cudaGetSymbolAddress((void**)&wo,  g_wo);
    cudaGetSymbolAddress((void**)&wgu, g_wgu);
    cudaGetSymbolAddress((void**)&wd,  g_wd);

    const int nMD = MM * DD;

    // weights -> fp16 (stacked, vectorized)
    w2h_k<<<(DD*DD/4+255)/256, 256>>>(wqkv,            Wq0, DD*DD/4);
    w2h_k<<<(DD*DD/4+255)/256, 256>>>(wqkv + DD*DD,    Wk0, DD*DD/4);
    w2h_k<<<(DD*DD/4+255)/256, 256>>>(wqkv + 2*DD*DD,  Wv0, DD*DD/4);
    w2h_k<<<(DD*DD/4+255)/256, 256>>>(wo,              Wo0, DD*DD/4);
    w2h_k<<<(FF*DD/4+255)/256, 256>>>(wgu,             Wg0, FF*DD/4);
    w2h_k<<<(FF*DD/4+255)/256, 256>>>(wgu + FF*DD,     Wu0, FF*DD/4);
    w2h_k<<<(FF*DD/4+255)/256, 256>>>(wd,              Wd0, FF*DD/4);

    // pass 1
    copy_k<<<(nMD+255)/256, 256>>>(cur, x, nMD);
    run_pass(wqkv, wo, wgu, wd, n1, n2, cur, xn, tmp, qa, ka, vt, ao, inv, sc, ph, gu, hh);
    copy_k<<<(nMD+255)/256, 256>>>(h1, cur, nMD);

    // x2 = h1 + beta*(h1 - x)
    x2_k<<<(nMD+255)/256, 256>>>(cur, h1, x, nMD);

    // pass 2
    run_pass(wqkv, wo, wgu, wd, n3, n4, cur, xn, tmp, qa, ka, vt, ao, inv, sc, ph, gu, hh);

    // out = clip(alpha*h1 + (1-alpha)*h2)
    final_k<<<(nMD+255)/256, 256>>>(out, h1, cur, nMD);
}

// round 10
// speedup vs baseline: 1.0428x; 1.0428x over previous
#include <cuda_runtime.h>
#include <cuda_fp16.h>
#include <math.h>
#include <stdint.h>

// ---------------- problem constants ----------------
#define BB   2
#define SS   1024
#define DD   2048
#define HH   16
#define FF   8192
#define DHD  128
#define HALF 64
#define MM   (BB*SS)          // 2048 rows
#define KAUG (2*DHD)          // 256 augmented K dim

#define HS    0.05f
#define BETA  0.3f
#define ALPHA 0.5f
#define CLIPV 10.0f
#define EPSV  1e-6f
#define SCALE 0.08838834764831845f   // 1/sqrt(128)
#define SQLAM 0.31622776601683794f   // sqrt(0.1)

// ---------------- static device scratch ----------------
static __device__ __align__(128) __half g_xn  [MM*DD];          // rmsnorm/mix out (GEMM A)
static __device__ __align__(128) __half g_tmp [MM*3*DD];        // QKV GEMM out (fp16)
static __device__ __align__(128) float  g_cur [MM*DD];          // pass-1 residual state (= h1)
static __device__ __align__(128) float  g_x2  [MM*DD];          // pass-2 residual state
static __device__ __align__(128) __half g_qa  [BB*HH*SS*KAUG];
static __device__ __align__(128) __half g_ka  [BB*HH*SS*KAUG];
static __device__ __align__(128) __half g_vt  [BB*HH*DHD*SS];   // per-head [DHD, S]
static __device__ __align__(128) float  g_ao  [BB*HH*SS*DHD];   // unnormalized PV out
static __device__ __align__(128) float  g_inv [BB*HH*SS];       // per-row 1/sum
static __device__ __align__(128) __half g_sc  [(long long)BB*HH*SS*SS];  // scores fp16
static __device__ __align__(128) __half g_ph  [(long long)BB*HH*SS*SS];  // unnorm probs fp16
static __device__ __align__(128) __half g_gu  [MM*2*FF];        // FFN gate|up out (fp16)
static __device__ __align__(128) __half g_hh  [MM*FF];          // FFN hidden (GEMM A)
// fp16 weights (stacked)
static __device__ __align__(128) __half g_wqkv[3*DD*DD];
static __device__ __align__(128) __half g_wo  [DD*DD];
static __device__ __align__(128) __half g_wgu [2*FF*DD];
static __device__ __align__(128) __half g_wd  [DD*FF];

// ---------------- helpers ----------------
__device__ __forceinline__ uint32_t smem_u32(const void* p) {
    uint32_t a;
    asm("{ .reg .u64 t; cvta.to.shared.u64 t, %1; cvt.u32.u64 %0, t; }" : "=r"(a) : "l"(p));
    return a;
}
__device__ __forceinline__ void cpasync16(uint32_t dst, const void* src) {
    asm volatile("cp.async.cg.shared.global [%0], [%1], 16;" :: "r"(dst), "l"(src));
}
#define CP_COMMIT()  asm volatile("cp.async.commit_group;" ::: "memory")
#define CP_WAIT2()   asm volatile("cp.async.wait_group 2;" ::: "memory")

__device__ __forceinline__ void ldmx4(uint32_t* r, uint32_t addr) {
    asm volatile("ldmatrix.sync.aligned.m8n8.x4.shared.b16 {%0,%1,%2,%3}, [%4];"
        : "=r"(r[0]), "=r"(r[1]), "=r"(r[2]), "=r"(r[3]) : "r"(addr));
}
__device__ __forceinline__ void mma16816(float* c, const uint32_t* a, uint32_t b0, uint32_t b1) {
    asm volatile("mma.sync.aligned.m16n8k16.row.col.f32.f16.f16.f32 "
        "{%0,%1,%2,%3}, {%4,%5,%6,%7}, {%8,%9}, {%0,%1,%2,%3};"
        : "+f"(c[0]), "+f"(c[1]), "+f"(c[2]), "+f"(c[3])
        : "r"(a[0]), "r"(a[1]), "r"(a[2]), "r"(a[3]), "r"(b0), "r"(b1));
}

// ---------------- fp16 tensor-core GEMM (R8 config: 8 warps, 32x64 tiles, 3-stage) ----------------
// C[M,N](TO) = A[M,K](f16) * B[N,K](f16)^T  (+= if ADD; ADD only with TO=float)
// CTA tile 128x128, chunk = 64 halves (128B rows), 3-stage cp.async, 2 CTA/SM.
// 8 warps (4m x 2n), warp tile 32x64, ldmatrix.x4, XOR-swizzled smem.
// TRI: blockIdx.x enumerates lower-triangle 128x128 blocks (causal scores).
// PVK: K limited to (blockIdx.y+1)*128 halves (causal PV).
#define HSTAGE 32768    // A:128 rows + B:128 rows, 128B each
#define HSMEM  (3*HSTAGE)

template<typename TO, bool ADD, bool TRI, bool PVK>
__global__ void __launch_bounds__(256, 2) hgemm(
    const __half* __restrict__ A, const __half* __restrict__ B, TO* __restrict__ C,
    int Kn, int Nn, long long sA, long long sB, long long sC)
{
    extern __shared__ __align__(128) char sm[];
    const uint32_t sbase = smem_u32(sm);

    int bi, bj;
    if (TRI) {
        int x = blockIdx.x, i = 0;
        while ((i + 1) * (i + 2) / 2 <= x) i++;
        bi = i; bj = x - i * (i + 1) / 2;
    } else { bi = blockIdx.y; bj = blockIdx.x; }

    A += (long long)blockIdx.z * sA + (long long)(bi * 128) * Kn;
    B += (long long)blockIdx.z * sB + (long long)(bj * 128) * Kn;
    C += (long long)blockIdx.z * sC;

    const int NC = PVK ? 2 * (blockIdx.y + 1) : (Kn >> 6);

    const int tid = threadIdx.x, warp = tid >> 5, lane = tid & 31;
    const int gid = lane >> 2, tig = lane & 3;
    const int wm = (warp & 3) * 32, wn = (warp >> 2) * 64;

    const int mi = lane >> 3, ri = lane & 7;
    const int fro = (mi & 1) * 8 + ri;
    const int khalf = mi >> 1;

    float acc[2][8][4];
#pragma unroll
    for (int mt = 0; mt < 2; mt++)
#pragma unroll
        for (int nt = 0; nt < 8; nt++)
#pragma unroll
            for (int j = 0; j < 4; j++) acc[mt][nt][j] = 0.f;

    const int lr = tid >> 3;
    const int lseg = tid & 7;

    // empty-commit padding when chunk >= NC keeps wait_group counts uniform
    auto load = [&](int chunk, int s) {
        if (chunk < NC) {
            const uint32_t st = sbase + (uint32_t)s * HSTAGE;
            const __half* Ag = A + chunk * 64;
            const __half* Bg = B + chunk * 64;
#pragma unroll
            for (int it = 0; it < 4; it++) {
                int r = lr + it * 32;
                uint32_t off = (uint32_t)(r * 128 + ((lseg ^ (r & 7)) << 4));
                cpasync16(st + off,         Ag + (long long)r * Kn + lseg * 8);
                cpasync16(st + 16384 + off, Bg + (long long)r * Kn + lseg * 8);
            }
        }
        CP_COMMIT();
    };

    load(0, 0);
    load(1, 1);
    load(2, 2);

    const int arow[2] = { wm + fro, wm + 16 + fro };
    const int brow[4] = { wn + fro, wn + 16 + fro, wn + 32 + fro, wn + 48 + fro };

    int s = 0;
    for (int c = 0; c < NC; c++) {
        CP_WAIT2();                       // stage s complete (2 groups may be pending)
        __syncthreads();

        const uint32_t st = sbase + (uint32_t)s * HSTAGE;
#pragma unroll
        for (int kb = 0; kb < 64; kb += 16) {
            const int ks = (kb >> 3) + khalf;
            uint32_t a[2][4], b[4][4];
#pragma unroll
            for (int mt = 0; mt < 2; mt++) {
                int r = arow[mt];
                ldmx4(a[mt], st + (uint32_t)(r * 128 + ((ks ^ (r & 7)) << 4)));
            }
#pragma unroll
            for (int np = 0; np < 4; np++) {
                int r = brow[np];
                ldmx4(b[np], st + 16384u + (uint32_t)(r * 128 + ((ks ^ (r & 7)) << 4)));
            }
#pragma unroll
            for (int mt = 0; mt < 2; mt++)
#pragma unroll
                for (int nt = 0; nt < 8; nt++)
                    mma16816(acc[mt][nt], a[mt], b[nt >> 1][nt & 1], b[nt >> 1][2 + (nt & 1)]);
        }
        __syncthreads();
        load(c + 3, s);                   // pads with empty commit past NC
        s = (s == 2) ? 0 : s + 1;
    }

    // epilogue
#pragma unroll
    for (int mt = 0; mt < 2; mt++) {
        int r0 = bi * 128 + wm + mt * 16 + gid;
#pragma unroll
        for (int nt = 0; nt < 8; nt++) {
            int cc = bj * 128 + wn + nt * 8 + 2 * tig;
            TO* p0 = C + (long long)r0 * Nn + cc;
            TO* p1 = p0 + 8 * (long long)Nn;
            if constexpr (sizeof(TO) == 2) {
                *(__half2*)p0 = __floats2half2_rn(acc[mt][nt][0], acc[mt][nt][1]);
                *(__half2*)p1 = __floats2half2_rn(acc[mt][nt][2], acc[mt][nt][3]);
            } else if (ADD) {
                p0[0] += acc[mt][nt][0]; p0[1] += acc[mt][nt][1];
                p1[0] += acc[mt][nt][2]; p1[1] += acc[mt][nt][3];
            } else {
                p0[0] = acc[mt][nt][0]; p0[1] = acc[mt][nt][1];
                p1[0] = acc[mt][nt][2]; p1[1] = acc[mt][nt][3];
            }
        }
    }
}

// ---------------- RMSNorm -> fp16 ----------------
__global__ void rmsnorm_k(const float* __restrict__ x, const float* __restrict__ sc,
                          __half* __restrict__ o)
{
    const int row = blockIdx.x;
    const float* xr = x + (long long)row * DD;
    __half*      orw = o + (long long)row * DD;
    float s = 0.f;
    for (int j = threadIdx.x; j < DD; j += 256) { float v = xr[j]; s += v * v; }
    __shared__ float red[256];
    red[threadIdx.x] = s; __syncthreads();
    for (int t = 128; t > 0; t >>= 1) {
        if (threadIdx.x < t) red[threadIdx.x] += red[threadIdx.x + t];
        __syncthreads();
    }
    float r = rsqrtf(red[0] * (1.0f / DD) + EPSV);
    for (int j = threadIdx.x; j < DD; j += 256) orw[j] = __float2half(xr[j] * r * sc[j]);
}

// ---------------- RoPE + augment (Q and K together) from tmp[M,3D] fp16 ----------------
__global__ void rope_aug2_k(const __half* __restrict__ t,
                            __half* __restrict__ qa, __half* __restrict__ ka)
{
    int idx = blockIdx.x * 256 + threadIdx.x;     // B*S*H*HALF threads
    int d = idx & 63;
    int h = (idx >> 6) & 15;
    int s = (idx >> 10) & 1023;
    int b = idx >> 20;
    const __half* row = t + ((long long)b * SS + s) * (3 * DD);
    float q1 = __half2float(row[h * DHD + d]);
    float q2 = __half2float(row[h * DHD + HALF + d]);
    float k1 = __half2float(row[DD + h * DHD + d]);
    float k2 = __half2float(row[DD + h * DHD + HALF + d]);
    float inv = __expf(-(float)d * (9.210340371976184f / 64.0f));
    float ang = (float)s * inv;
    float cs, sn; __sincosf(ang, &sn, &cs);
    long long base = (((long long)(b * HH + h)) * SS + s) * KAUG;
    float qo1 = q1 * cs - q2 * sn, qo2 = q1 * sn + q2 * cs;
    float ko1 = k1 * cs - k2 * sn, ko2 = k1 * sn + k2 * cs;
    qa[base + d]              = __float2half(qo1);
    qa[base + HALF + d]       = __float2half(qo2);
    qa[base + DHD + d]        = __float2half(SQLAM * qo1 * qo1);
    qa[base + DHD + HALF + d] = __float2half(SQLAM * qo2 * qo2);
    ka[base + d]              = __float2half(ko1);
    ka[base + HALF + d]       = __float2half(ko2);
    ka[base + DHD + d]        = __float2half(SQLAM * ko1 * ko1);
    ka[base + DHD + HALF + d] = __float2half(SQLAM * ko2 * ko2);
}

// ---------------- V transpose from tmp[M,3D] fp16 -> per-head [DHD,S] ----------------
__global__ void vt_k(const __half* __restrict__ t, __half* __restrict__ out)
{
    __shared__ __half tl[32][33];
    int bh = blockIdx.z;
    int b = bh >> 4, h = bh & 15;
    int s0 = blockIdx.x * 32, d0 = blockIdx.y * 32;
    int tx = threadIdx.x & 31, ty = threadIdx.x >> 5;
    for (int i = ty; i < 32; i += 8) {
        int s = s0 + i, d = d0 + tx;
        tl[i][tx] = t[((long long)(b * SS + s)) * (3 * DD) + 2 * DD + h * DHD + d];
    }
    __syncthreads();
    for (int i = ty; i < 32; i += 8) {
        int d = d0 + i, s = s0 + tx;
        out[((long long)bh * DHD + d) * SS + s] = tl[tx][i];
    }
}

// ---------------- causal softmax: fp16 scores in, single exp, unnormalized out ----------------
__global__ void softmax_k(const __half* __restrict__ sc, __half* __restrict__ ph,
                          float* __restrict__ inv)
{
    long long row = blockIdx.x;
    int i = (int)(row % SS);
    int lim = i | 127;                    // zero-fill out to PV block boundary
    const __half* p = sc + row * SS;
    __half* q = ph + row * SS;
    int tid = threadIdx.x;
    __shared__ float red[256];

    float v[4];
    float m = -1e30f;
#pragma unroll
    for (int k = 0; k < 4; k++) {
        int j = tid + 256 * k;
        v[k] = (j <= i) ? __half2float(p[j]) * SCALE : -1e30f;
        m = fmaxf(m, v[k]);
    }
    red[tid] = m; __syncthreads();
    for (int t = 128; t > 0; t >>= 1) {
        if (tid < t) red[tid] = fmaxf(red[tid], red[tid + t]);
        __syncthreads();
    }
    m = red[0]; __syncthreads();

    float sum = 0.f;
#pragma unroll
    for (int k = 0; k < 4; k++) {
        int j = tid + 256 * k;
        if (j <= i) {
            float e = __expf(v[k] - m);
            q[j] = __float2half(e);
            sum += e;
        } else if (j <= lim) {
            q[j] = __half(0.f);
        }
    }
    red[tid] = sum; __syncthreads();
    for (int t = 128; t > 0; t >>= 1) {
        if (tid < t) red[tid] += red[tid + t];
        __syncthreads();
    }
    if (tid == 0) inv[row] = 1.f / red[0];
}

// ---------------- normalize + hadamard mix + transpose -> fp16 [M,D] ----------------
__global__ void mix_transpose_k(const float* __restrict__ ao, const float* __restrict__ inv,
                                __half* __restrict__ out)
{
    int idx = blockIdx.x * 256 + threadIdx.x;
    int d  = idx & 127;
    int s  = (idx >> 7) & 1023;
    int bh = idx >> 17;
    int h = bh & 15, b = bh >> 4;
    float iv = inv[(long long)bh * SS + s];
    float v  = ao[idx] * iv;
    float pv = ao[(idx - d) | ((d + 127) & 127)] * iv;
    out[((long long)(b * SS + s)) * DD + h * DHD + d] = __float2half(v * (1.f + HS * pv));
}

// ---------------- fused silu*up + hadamard mix, chunked (9 exps / 8 outputs) ----------------
__global__ void silu_mix_k(const __half* __restrict__ gu, __half* __restrict__ hh)
{
    int t = blockIdx.x * 256 + threadIdx.x;       // M*F/8 threads
    int m = t >> 10;                               // F/8 = 1024 chunks per row
    int c0 = (t & 1023) << 3;
    const __half* grow = gu + (long long)m * (2 * FF);
    const __half* urow = grow + FF;
    int pc = (c0 + FF - 1) & (FF - 1);
    float gp = __half2float(grow[pc]);
    float up = __half2float(urow[pc]);
    float hprev = gp / (1.f + __expf(-gp)) * up;
    __half* orow = hh + (long long)m * FF + c0;
#pragma unroll
    for (int k = 0; k < 8; k++) {
        float g = __half2float(grow[c0 + k]);
        float u = __half2float(urow[c0 + k]);
        float h = g / (1.f + __expf(-g)) * u;
        orow[k] = __float2half(h * (1.f + HS * hprev));
        hprev = h;
    }
}

// ---------------- misc elementwise ----------------
__global__ void copy_k(float* __restrict__ dst, const float* __restrict__ src, int n)
{ int i = blockIdx.x * 256 + threadIdx.x; if (i < n) dst[i] = src[i]; }

// vectorized fp32->fp16 (n divisible by 4)
__global__ void w2h_k(__half* __restrict__ dst, const float* __restrict__ src, int n4)
{
    int i = blockIdx.x * 256 + threadIdx.x;
    if (i < n4) {
        float4 v = ((const float4*)src)[i];
        __half2 lo = __floats2half2_rn(v.x, v.y);
        __half2 hi = __floats2half2_rn(v.z, v.w);
        ((uint2*)dst)[i] = make_uint2(*(uint32_t*)&lo, *(uint32_t*)&hi);
    }
}

__global__ void x2_k(float* __restrict__ dst, const float* __restrict__ h1,
                     const float* __restrict__ x, int n)
{ int i = blockIdx.x * 256 + threadIdx.x; if (i < n) dst[i] = (1.f + BETA) * h1[i] - BETA * x[i]; }

__global__ void final_k(float* __restrict__ out, const float* __restrict__ h1,
                        const float* __restrict__ h2, int n)
{
    int i = blockIdx.x * 256 + threadIdx.x;
    if (i < n) {
        float v = ALPHA * h1[i] + (1.f - ALPHA) * h2[i];
        out[i] = fminf(fmaxf(v, -CLIPV), CLIPV);
    }
}

// ---------------- host orchestration ----------------
static void run_pass(const __half* wqkv, const __half* wo, const __half* wgu, const __half* wd,
                     const float* na, const float* nb,
                     float* cur, __half* xn, __half* tmp,
                     __half* qa, __half* ka, __half* vt, float* ao, float* inv,
                     __half* sc, __half* ph, __half* gu, __half* hh)
{
    const int nMD = MM * DD, nMF = MM * FF;

    rmsnorm_k<<<MM, 256>>>(cur, na, xn);

    // fused QKV: [M, 3D](fp16) = xn * wqkv^T
    hgemm<__half,false,false,false><<<dim3(3*DD/128, MM/128, 1), 256, HSMEM>>>(
        xn, wqkv, tmp, DD, 3*DD, 0, 0, 0);
    rope_aug2_k<<<(BB*SS*HH*HALF)/256, 256>>>(tmp, qa, ka);
    vt_k<<<dim3(SS/32, DHD/32, BB*HH), 256>>>(tmp, vt);

    // causal scores (fp16 out): lower-triangle blocks only
    hgemm<__half,false,true,false><<<dim3(36, 1, BB*HH), 256, HSMEM>>>(
        qa, ka, sc, KAUG, SS,
        (long long)SS*KAUG, (long long)SS*KAUG, (long long)SS*SS);
    softmax_k<<<BB*HH*SS, 256>>>(sc, ph, inv);
    // PV with causal K truncation (unnormalized probs)
    hgemm<float,false,false,true><<<dim3(1, SS/128, BB*HH), 256, HSMEM>>>(
        ph, vt, ao, SS, DHD,
        (long long)SS*SS, (long long)SS*DHD, (long long)SS*DHD);

    mix_transpose_k<<<nMD/256, 256>>>(ao, inv, xn);
    hgemm<float,true,false,false><<<dim3(DD/128, MM/128, 1), 256, HSMEM>>>(
        xn, wo, cur, DD, DD, 0, 0, 0);

    rmsnorm_k<<<MM, 256>>>(cur, nb, xn);
    // fused gate|up: [M, 2F](fp16)
    hgemm<__half,false,false,false><<<dim3(2*FF/128, MM/128, 1), 256, HSMEM>>>(
        xn, wgu, gu, DD, 2*FF, 0, 0, 0);
    silu_mix_k<<<nMF/8/256, 256>>>(gu, hh);
    hgemm<float,true,false,false><<<dim3(DD/128, MM/128, 1), 256, HSMEM>>>(
        hh, wd, cur, FF, DD, 0, 0, 0);
}

extern "C" void kernel_launch(void* const* d_in, const int* in_sizes, int n_in,
                              void* d_out, int out_size)
{
    (void)in_sizes; (void)n_in; (void)out_size;
    const float* x   = (const float*)d_in[0];
    const float* Wq0 = (const float*)d_in[1];
    const float* Wk0 = (const float*)d_in[2];
    const float* Wv0 = (const float*)d_in[3];
    const float* Wo0 = (const float*)d_in[4];
    // d_in[5] = gate_w: unused (rotate_half invariance => o2 == o1)
    const float* n1 = (const float*)d_in[6];
    const float* n2 = (const float*)d_in[7];
    const float* n3 = (const float*)d_in[8];
    const float* n4 = (const float*)d_in[9];
    const float* Wg0 = (const float*)d_in[10];
    const float* Wu0 = (const float*)d_in[11];
    const float* Wd0 = (const float*)d_in[12];
    float* out = (float*)d_out;

    cudaFuncSetAttribute(hgemm<__half,false,false,false>, cudaFuncAttributeMaxDynamicSharedMemorySize, HSMEM);
    cudaFuncSetAttribute(hgemm<float,true,false,false>,   cudaFuncAttributeMaxDynamicSharedMemorySize, HSMEM);
    cudaFuncSetAttribute(hgemm<__half,false,true,false>,  cudaFuncAttributeMaxDynamicSharedMemorySize, HSMEM);
    cudaFuncSetAttribute(hgemm<float,false,false,true>,   cudaFuncAttributeMaxDynamicSharedMemorySize, HSMEM);

    __half *xn, *tmp, *qa, *ka, *vt, *sc, *ph, *gu, *hh, *wqkv, *wo, *wgu, *wd;
    float *cur, *x2, *ao, *inv;
    cudaGetSymbolAddress((void**)&xn,  g_xn);
    cudaGetSymbolAddress((void**)&tmp, g_tmp);
    cudaGetSymbolAddress((void**)&cur, g_cur);
    cudaGetSymbolAddress((void**)&x2,  g_x2);
    cudaGetSymbolAddress((void**)&qa,  g_qa);
    cudaGetSymbolAddress((void**)&ka,  g_ka);
    cudaGetSymbolAddress((void**)&vt,  g_vt);
    cudaGetSymbolAddress((void**)&ao,  g_ao);
    cudaGetSymbolAddress((void**)&inv, g_inv);
    cudaGetSymbolAddress((void**)&sc,  g_sc);
    cudaGetSymbolAddress((void**)&ph,  g_ph);
    cudaGetSymbolAddress((void**)&gu,  g_gu);
    cudaGetSymbolAddress((void**)&hh,  g_hh);
    cudaGetSymbolAddress((void**)&wqkv,g_wqkv);
    cudaGetSymbolAddress((void**)&wo,  g_wo);
    cudaGetSymbolAddress((void**)&wgu, g_wgu);
    cudaGetSymbolAddress((void**)&wd,  g_wd);

    const int nMD = MM * DD;

    // weights -> fp16 (stacked, vectorized)
    w2h_k<<<(DD*DD/4+255)/256, 256>>>(wqkv,            Wq0, DD*DD/4);
    w2h_k<<<(DD*DD/4+255)/256, 256>>>(wqkv + DD*DD,    Wk0, DD*DD/4);
    w2h_k<<<(DD*DD/4+255)/256, 256>>>(wqkv + 2*DD*DD,  Wv0, DD*DD/4);
    w2h_k<<<(DD*DD/4+255)/256, 256>>>(wo,              Wo0, DD*DD/4);
    w2h_k<<<(FF*DD/4+255)/256, 256>>>(wgu,             Wg0, FF*DD/4);
    w2h_k<<<(FF*DD/4+255)/256, 256>>>(wgu + FF*DD,     Wu0, FF*DD/4);
    w2h_k<<<(FF*DD/4+255)/256, 256>>>(wd,              Wd0, FF*DD/4);

    // pass 1 (accumulates into cur; cur becomes h1 — no copy needed)
    copy_k<<<(nMD+255)/256, 256>>>(cur, x, nMD);
    run_pass(wqkv, wo, wgu, wd, n1, n2, cur, xn, tmp, qa, ka, vt, ao, inv, sc, ph, gu, hh);

    // x2 = h1 + beta*(h1 - x)  -> separate buffer, preserving cur (= h1)
    x2_k<<<(nMD+255)/256, 256>>>(x2, cur, x, nMD);

    // pass 2 (accumulates into x2)
    run_pass(wqkv, wo, wgu, wd, n3, n4, x2, xn, tmp, qa, ka, vt, ao, inv, sc, ph, gu, hh);

    // out = clip(alpha*h1 + (1-alpha)*h2)
    final_k<<<(nMD+255)/256, 256>>>(out, cur, x2, nMD);
}